// round 1
// baseline (speedup 1.0000x reference)
#include <cuda_runtime.h>
#include <cstdint>

#define N_NODES 100000
#define N_EDGES 1600000
#define DIM 128

// Scratch for h = x@W + b  (51.2 MB). Static __device__ array per allocation rules.
__device__ float g_h[(size_t)N_NODES * DIM];

// ---------------------------------------------------------------------------
// Kernel 1: zero the output (harness poisons d_out with 0xAA).
// ---------------------------------------------------------------------------
__global__ void zero_kernel(float4* __restrict__ out, int n4) {
    int i = blockIdx.x * blockDim.x + threadIdx.x;
    if (i < n4) out[i] = make_float4(0.f, 0.f, 0.f, 0.f);
}

// ---------------------------------------------------------------------------
// Kernel 2: h = x @ W + b.  Tile: 64 rows x 128 cols per block, 256 threads.
// Thread (ty in 0..7, tx in 0..31) computes 8 rows x 4 cols.
// x tile staged in smem (warp-broadcast reads); W streamed as float4 via L1.
// ---------------------------------------------------------------------------
#define TM 64
__global__ __launch_bounds__(256) void gemm_kernel(
    const float* __restrict__ x, const float* __restrict__ W,
    const float* __restrict__ b, float* __restrict__ h)
{
    __shared__ float Xs[TM][DIM];   // 32 KB

    const int tid = threadIdx.x;
    const int tx  = tid & 31;   // column group: cols [tx*4, tx*4+4)
    const int ty  = tid >> 5;   // row group: rows [ty*8, ty*8+8) within tile
    const int block_row = blockIdx.x * TM;

    // Load x tile: 64*128 floats = 2048 float4, 8 per thread. Guard tail block.
    {
        const float4* xg = reinterpret_cast<const float4*>(x) + (size_t)block_row * (DIM / 4);
        float4* xs4 = reinterpret_cast<float4*>(&Xs[0][0]);
        #pragma unroll
        for (int i = 0; i < 8; i++) {
            int idx = tid + i * 256;              // float4 index within tile
            int row = block_row + (idx >> 5);     // 32 float4 per row
            xs4[idx] = (row < N_NODES) ? xg[idx] : make_float4(0.f, 0.f, 0.f, 0.f);
        }
    }
    __syncthreads();

    float acc[8][4];
    {
        float4 bv = reinterpret_cast<const float4*>(b)[tx];
        #pragma unroll
        for (int r = 0; r < 8; r++) {
            acc[r][0] = bv.x; acc[r][1] = bv.y; acc[r][2] = bv.z; acc[r][3] = bv.w;
        }
    }

    const float4* W4 = reinterpret_cast<const float4*>(W);
    #pragma unroll 4
    for (int k = 0; k < DIM; k++) {
        float4 wv = __ldg(W4 + k * (DIM / 4) + tx);
        #pragma unroll
        for (int r = 0; r < 8; r++) {
            float xv = Xs[ty * 8 + r][k];   // warp-broadcast
            acc[r][0] += xv * wv.x;
            acc[r][1] += xv * wv.y;
            acc[r][2] += xv * wv.z;
            acc[r][3] += xv * wv.w;
        }
    }

    #pragma unroll
    for (int r = 0; r < 8; r++) {
        int row = block_row + ty * 8 + r;
        if (row < N_NODES) {
            reinterpret_cast<float4*>(h + (size_t)row * DIM)[tx] =
                make_float4(acc[r][0], acc[r][1], acc[r][2], acc[r][3]);
        }
    }
}

// ---------------------------------------------------------------------------
// Kernel 3: edge scatter. One warp per edge; lane l handles floats [4l, 4l+4).
// out[rows[e]] += vals[e] * h[cols[e]]  via red.global.add.v4.f32 (no return).
// ---------------------------------------------------------------------------
__global__ __launch_bounds__(256) void scatter_kernel(
    const float* __restrict__ vals, const int* __restrict__ rows,
    const int* __restrict__ cols, const float* __restrict__ h,
    float* __restrict__ out)
{
    const int e = blockIdx.x * 8 + (threadIdx.x >> 5);
    if (e >= N_EDGES) return;
    const int lane = threadIdx.x & 31;

    const int r = __ldg(rows + e);
    const int c = __ldg(cols + e);
    const float v = __ldg(vals + e);

    float4 hv = __ldg(reinterpret_cast<const float4*>(h + (size_t)c * DIM) + lane);
    float* dst = out + (size_t)r * DIM + lane * 4;
    asm volatile("red.global.add.v4.f32 [%0], {%1, %2, %3, %4};"
                 :: "l"(dst), "f"(hv.x * v), "f"(hv.y * v), "f"(hv.z * v), "f"(hv.w * v)
                 : "memory");
}

// ---------------------------------------------------------------------------
extern "C" void kernel_launch(void* const* d_in, const int* in_sizes, int n_in,
                              void* d_out, int out_size)
{
    const float* x    = (const float*)d_in[0];   // [N_NODES, DIM]
    const float* W    = (const float*)d_in[1];   // [DIM, DIM]
    const float* b    = (const float*)d_in[2];   // [DIM]
    const float* vals = (const float*)d_in[3];   // [N_EDGES]
    const int*   rows = (const int*)d_in[4];     // [N_EDGES]
    const int*   cols = (const int*)d_in[5];     // [N_EDGES]
    float* out = (float*)d_out;                  // [N_NODES, DIM]

    float* h;
    cudaGetSymbolAddress((void**)&h, g_h);

    // Zero output (independent of GEMM).
    {
        int n4 = (N_NODES * DIM) / 4;            // 3,200,000 float4
        zero_kernel<<<(n4 + 255) / 256, 256>>>((float4*)out, n4);
    }

    // h = x @ W + b
    {
        int grid = (N_NODES + TM - 1) / TM;      // 1563
        gemm_kernel<<<grid, 256>>>(x, W, b, h);
    }

    // Edge scatter (depends on both; stream-ordered).
    {
        int grid = (N_EDGES + 7) / 8;            // 200,000 blocks, 8 edges each
        scatter_kernel<<<grid, 256>>>(vals, rows, cols, h, out);
    }
}

// round 2
// speedup vs baseline: 1.5951x; 1.5951x over previous
#include <cuda_runtime.h>
#include <cstdint>

#define N_NODES 100000
#define N_EDGES 1600000
#define DIM 128
#define SCAN_B 1024
#define N_SCAN_BLOCKS ((N_NODES + SCAN_B - 1) / SCAN_B)   // 98

// Static device scratch (allocation rules forbid cudaMalloc).
__device__ float g_h[(size_t)N_NODES * DIM];        // 51.2 MB: h = x@W + b
__device__ int   g_cnt[N_NODES];                    // per-node in-degree
__device__ int   g_off[N_NODES + 1];                // CSR offsets
__device__ int   g_cursor[N_NODES];                 // fill cursors
__device__ int   g_bsum[N_SCAN_BLOCKS];             // scan block sums
__device__ uint2 g_edge[N_EDGES];                   // packed (col, val-bits)

// ---------------------------------------------------------------------------
// CSR build step 0: zero counters.
// ---------------------------------------------------------------------------
__global__ void zero_cnt_kernel() {
    int i = blockIdx.x * blockDim.x + threadIdx.x;
    if (i < N_NODES) g_cnt[i] = 0;
    if (i == 0) g_off[N_NODES] = N_EDGES;
}

// ---------------------------------------------------------------------------
// CSR build step 1: histogram of rows.
// ---------------------------------------------------------------------------
__global__ void hist_kernel(const int* __restrict__ rows) {
    int e = blockIdx.x * blockDim.x + threadIdx.x;
    if (e < N_EDGES) atomicAdd(&g_cnt[rows[e]], 1);
}

// ---------------------------------------------------------------------------
// CSR build step 2a: per-block exclusive scan (Hillis-Steele in smem).
// ---------------------------------------------------------------------------
__global__ __launch_bounds__(SCAN_B) void scan1_kernel() {
    __shared__ int s[SCAN_B];
    int i = blockIdx.x * SCAN_B + threadIdx.x;
    int v = (i < N_NODES) ? g_cnt[i] : 0;
    s[threadIdx.x] = v;
    __syncthreads();
    #pragma unroll
    for (int d = 1; d < SCAN_B; d <<= 1) {
        int t = (threadIdx.x >= d) ? s[threadIdx.x - d] : 0;
        __syncthreads();
        s[threadIdx.x] += t;
        __syncthreads();
    }
    int incl = s[threadIdx.x];
    if (i < N_NODES) g_off[i] = incl - v;               // exclusive within block
    if (threadIdx.x == SCAN_B - 1) g_bsum[blockIdx.x] = incl;
}

// CSR build step 2b: scan the 98 block sums (one block of 128).
__global__ __launch_bounds__(128) void scan2_kernel() {
    __shared__ int s[128];
    int v = (threadIdx.x < N_SCAN_BLOCKS) ? g_bsum[threadIdx.x] : 0;
    s[threadIdx.x] = v;
    __syncthreads();
    #pragma unroll
    for (int d = 1; d < 128; d <<= 1) {
        int t = (threadIdx.x >= d) ? s[threadIdx.x - d] : 0;
        __syncthreads();
        s[threadIdx.x] += t;
        __syncthreads();
    }
    if (threadIdx.x < N_SCAN_BLOCKS) g_bsum[threadIdx.x] = s[threadIdx.x] - v;
}

// CSR build step 2c: add block offsets; init cursors.
__global__ __launch_bounds__(SCAN_B) void scan3_kernel() {
    int i = blockIdx.x * SCAN_B + threadIdx.x;
    if (i < N_NODES) {
        int o = g_off[i] + g_bsum[blockIdx.x];
        g_off[i]    = o;
        g_cursor[i] = o;
    }
}

// ---------------------------------------------------------------------------
// CSR build step 3: fill packed edge list (col, val) per destination node.
// ---------------------------------------------------------------------------
__global__ void fill_kernel(const int* __restrict__ rows,
                            const int* __restrict__ cols,
                            const float* __restrict__ vals) {
    int e = blockIdx.x * blockDim.x + threadIdx.x;
    if (e < N_EDGES) {
        int pos = atomicAdd(&g_cursor[rows[e]], 1);
        g_edge[pos] = make_uint2((unsigned)cols[e], __float_as_uint(vals[e]));
    }
}

// ---------------------------------------------------------------------------
// h = x @ W + b.  64 rows x 128 cols per 256-thread block; 8x4 per thread.
// ---------------------------------------------------------------------------
#define TM 64
__global__ __launch_bounds__(256) void gemm_kernel(
    const float* __restrict__ x, const float* __restrict__ W,
    const float* __restrict__ b)
{
    __shared__ float Xs[TM][DIM];

    const int tid = threadIdx.x;
    const int tx  = tid & 31;
    const int ty  = tid >> 5;
    const int block_row = blockIdx.x * TM;

    {
        const float4* xg = reinterpret_cast<const float4*>(x) + (size_t)block_row * (DIM / 4);
        float4* xs4 = reinterpret_cast<float4*>(&Xs[0][0]);
        #pragma unroll
        for (int i = 0; i < 8; i++) {
            int idx = tid + i * 256;
            int row = block_row + (idx >> 5);
            xs4[idx] = (row < N_NODES) ? xg[idx] : make_float4(0.f, 0.f, 0.f, 0.f);
        }
    }
    __syncthreads();

    float acc[8][4];
    {
        float4 bv = reinterpret_cast<const float4*>(b)[tx];
        #pragma unroll
        for (int r = 0; r < 8; r++) {
            acc[r][0] = bv.x; acc[r][1] = bv.y; acc[r][2] = bv.z; acc[r][3] = bv.w;
        }
    }

    const float4* W4 = reinterpret_cast<const float4*>(W);
    #pragma unroll 4
    for (int k = 0; k < DIM; k++) {
        float4 wv = __ldg(W4 + k * (DIM / 4) + tx);
        #pragma unroll
        for (int r = 0; r < 8; r++) {
            float xv = Xs[ty * 8 + r][k];
            acc[r][0] += xv * wv.x;
            acc[r][1] += xv * wv.y;
            acc[r][2] += xv * wv.z;
            acc[r][3] += xv * wv.w;
        }
    }

    #pragma unroll
    for (int r = 0; r < 8; r++) {
        int row = block_row + ty * 8 + r;
        if (row < N_NODES) {
            reinterpret_cast<float4*>(g_h + (size_t)row * DIM)[tx] =
                make_float4(acc[r][0], acc[r][1], acc[r][2], acc[r][3]);
        }
    }
}

// ---------------------------------------------------------------------------
// Pull-gather: one warp per node. lane l owns floats [4l, 4l+4) of the row.
// acc = sum over incoming edges of val * h[col]; single coalesced store.
// ---------------------------------------------------------------------------
__global__ __launch_bounds__(256) void gather_kernel(float* __restrict__ out) {
    const int node = (blockIdx.x * 256 + threadIdx.x) >> 5;
    if (node >= N_NODES) return;
    const int lane = threadIdx.x & 31;

    const int beg = __ldg(&g_off[node]);
    const int end = __ldg(&g_off[node + 1]);

    const float4* h4 = reinterpret_cast<const float4*>(g_h);
    float4 acc = make_float4(0.f, 0.f, 0.f, 0.f);

    int i = beg;
    // Unroll by 2: two independent edge->h load chains in flight.
    for (; i + 1 < end; i += 2) {
        uint2 e0 = __ldg(&g_edge[i]);
        uint2 e1 = __ldg(&g_edge[i + 1]);
        float4 a0 = __ldg(h4 + (size_t)e0.x * 32 + lane);
        float4 a1 = __ldg(h4 + (size_t)e1.x * 32 + lane);
        float v0 = __uint_as_float(e0.y);
        float v1 = __uint_as_float(e1.y);
        acc.x += v0 * a0.x; acc.y += v0 * a0.y;
        acc.z += v0 * a0.z; acc.w += v0 * a0.w;
        acc.x += v1 * a1.x; acc.y += v1 * a1.y;
        acc.z += v1 * a1.z; acc.w += v1 * a1.w;
    }
    if (i < end) {
        uint2 e0 = __ldg(&g_edge[i]);
        float4 a0 = __ldg(h4 + (size_t)e0.x * 32 + lane);
        float v0 = __uint_as_float(e0.y);
        acc.x += v0 * a0.x; acc.y += v0 * a0.y;
        acc.z += v0 * a0.z; acc.w += v0 * a0.w;
    }

    reinterpret_cast<float4*>(out)[(size_t)node * 32 + lane] = acc;
}

// ---------------------------------------------------------------------------
extern "C" void kernel_launch(void* const* d_in, const int* in_sizes, int n_in,
                              void* d_out, int out_size)
{
    const float* x    = (const float*)d_in[0];
    const float* W    = (const float*)d_in[1];
    const float* b    = (const float*)d_in[2];
    const float* vals = (const float*)d_in[3];
    const int*   rows = (const int*)d_in[4];
    const int*   cols = (const int*)d_in[5];
    float* out = (float*)d_out;

    const int EB = (N_EDGES + 255) / 256;     // edge-grid, 6250 blocks
    const int NB = (N_NODES + 255) / 256;     // node-grid

    // CSR build
    zero_cnt_kernel<<<NB, 256>>>();
    hist_kernel<<<EB, 256>>>(rows);
    scan1_kernel<<<N_SCAN_BLOCKS, SCAN_B>>>();
    scan2_kernel<<<1, 128>>>();
    scan3_kernel<<<N_SCAN_BLOCKS, SCAN_B>>>();
    fill_kernel<<<EB, 256>>>(rows, cols, vals);

    // h = x @ W + b
    gemm_kernel<<<(N_NODES + TM - 1) / TM, 256>>>(x, W, b);

    // out[n] = sum over edges into n of val * h[col]
    gather_kernel<<<(N_NODES * 32 + 255) / 256, 256>>>(out);
}